// round 1
// baseline (speedup 1.0000x reference)
#include <cuda_runtime.h>
#include <math.h>

// Problem dims
#define BATCH 4096
#define TSEQ  256
#define DIN   64
#define HID   256

// Ping-pong recurrent state scratch (allowed: __device__ globals, no allocs)
__device__ float g_h1[2][BATCH * HID];
__device__ float g_h2[2][BATCH * HID];

// ---------------------------------------------------------------------------
// Copy harness-provided initial states into our ping-pong buffers (slot 0).
__global__ void init_states(const float* __restrict__ h1,
                            const float* __restrict__ h2) {
    int n = BATCH * HID;
    for (int i = blockIdx.x * blockDim.x + threadIdx.x; i < n;
         i += gridDim.x * blockDim.x) {
        g_h1[0][i] = h1[i];
        g_h2[0][i] = h2[i];
    }
}

// Final states -> tail of d_out (after 256 steps final state is in slot 0).
__global__ void write_states(float* __restrict__ out) {
    int n = BATCH * HID;
    for (int i = blockIdx.x * blockDim.x + threadIdx.x; i < n;
         i += gridDim.x * blockDim.x) {
        out[i]     = g_h1[0][i];
        out[n + i] = g_h2[0][i];
    }
}

// ---------------------------------------------------------------------------
// Fused GRU layer step.
//   For each (b, j):  s_r = b_ih[j]+b_hh[j] + x.Wih_r[j] + h.Whh_r[j]
//                     s_z = (same, +H rows)
//                     i_n = b_ih[2H+j] + x.Wih_n[j]
//                     h_n = b_hh[2H+j] + h.Whh_n[j]
//   r=sig(s_r), z=sig(s_z), n=tanh(i_n + r*h_n), h' = (1-z)*n + z*h
//
// Block tile: 64 batches x 32 j-columns (=> 96 gate columns staged).
// 256 threads, each computes 4b x 2j outputs, 4 accumulators each.
// layer==0: X=Xext (x_t, row stride ldx), state = g_h1
// layer==1: X=g_h1[nxt] (this step's new h1), state = g_h2
template <int DX>
__global__ void __launch_bounds__(256)
gru_layer(const float* __restrict__ Xext, int ldx, int layer, int cur,
          const float* __restrict__ Wih, const float* __restrict__ Whh,
          const float* __restrict__ bih, const float* __restrict__ bhh) {
    const int nxt = cur ^ 1;
    const float* X    = (layer == 0) ? Xext : g_h1[nxt];
    const int    xld  = (layer == 0) ? ldx  : HID;
    const float* Hold = (layer == 0) ? g_h1[cur] : g_h2[cur];
    float*       Hnew = (layer == 0) ? g_h1[nxt] : g_h2[nxt];

    const int tx = threadIdx.x;          // 0..255
    const int jl = (tx & 15) * 2;        // 0..30 (2 j per thread)
    const int bl = (tx >> 4) * 4;        // 0..60 (4 b per thread)
    const int b0 = blockIdx.x * 64;
    const int j0 = blockIdx.y * 32;

    __shared__ float sX[64][17];
    __shared__ float sW[96][17];

    float s_r[4][2], s_z[4][2], a_in[4][2], a_hn[4][2];

    // init accumulators with biases
    #pragma unroll
    for (int c = 0; c < 2; c++) {
        int j = j0 + jl + c;
        float vr = bih[j]           + bhh[j];
        float vz = bih[HID + j]     + bhh[HID + j];
        float vi = bih[2 * HID + j];
        float vh = bhh[2 * HID + j];
        #pragma unroll
        for (int i = 0; i < 4; i++) {
            s_r[i][c] = vr; s_z[i][c] = vz; a_in[i][c] = vi; a_hn[i][c] = vh;
        }
    }

    // ---------------- Phase 1: input part (K = DX, weights Wih) -----------
    for (int k0 = 0; k0 < DX; k0 += 16) {
        for (int idx = tx; idx < 64 * 16; idx += 256) {
            int b = idx >> 4, k = idx & 15;
            sX[b][k] = X[(size_t)(b0 + b) * xld + k0 + k];
        }
        for (int idx = tx; idx < 96 * 16; idx += 256) {
            int r = idx >> 4, k = idx & 15;
            int g = r >> 5, jj = r & 31;
            sW[r][k] = Wih[(size_t)(g * HID + j0 + jj) * DX + k0 + k];
        }
        __syncthreads();
        #pragma unroll
        for (int kk = 0; kk < 16; kk++) {
            float xv[4];
            #pragma unroll
            for (int i = 0; i < 4; i++) xv[i] = sX[bl + i][kk];
            #pragma unroll
            for (int c = 0; c < 2; c++) {
                float wr = sW[jl + c][kk];
                float wz = sW[32 + jl + c][kk];
                float wn = sW[64 + jl + c][kk];
                #pragma unroll
                for (int i = 0; i < 4; i++) {
                    s_r[i][c]  += xv[i] * wr;
                    s_z[i][c]  += xv[i] * wz;
                    a_in[i][c] += xv[i] * wn;
                }
            }
        }
        __syncthreads();
    }

    // ---------------- Phase 2: hidden part (K = HID, weights Whh) ---------
    for (int k0 = 0; k0 < HID; k0 += 16) {
        for (int idx = tx; idx < 64 * 16; idx += 256) {
            int b = idx >> 4, k = idx & 15;
            sX[b][k] = Hold[(size_t)(b0 + b) * HID + k0 + k];
        }
        for (int idx = tx; idx < 96 * 16; idx += 256) {
            int r = idx >> 4, k = idx & 15;
            int g = r >> 5, jj = r & 31;
            sW[r][k] = Whh[(size_t)(g * HID + j0 + jj) * HID + k0 + k];
        }
        __syncthreads();
        #pragma unroll
        for (int kk = 0; kk < 16; kk++) {
            float xv[4];
            #pragma unroll
            for (int i = 0; i < 4; i++) xv[i] = sX[bl + i][kk];
            #pragma unroll
            for (int c = 0; c < 2; c++) {
                float wr = sW[jl + c][kk];
                float wz = sW[32 + jl + c][kk];
                float wn = sW[64 + jl + c][kk];
                #pragma unroll
                for (int i = 0; i < 4; i++) {
                    s_r[i][c]  += xv[i] * wr;
                    s_z[i][c]  += xv[i] * wz;
                    a_hn[i][c] += xv[i] * wn;
                }
            }
        }
        __syncthreads();
    }

    // ---------------- Epilogue: gates + state update ----------------------
    #pragma unroll
    for (int i = 0; i < 4; i++) {
        int b = b0 + bl + i;
        #pragma unroll
        for (int c = 0; c < 2; c++) {
            int j = j0 + jl + c;
            float r = 1.0f / (1.0f + expf(-s_r[i][c]));
            float z = 1.0f / (1.0f + expf(-s_z[i][c]));
            float n = tanhf(a_in[i][c] + r * a_hn[i][c]);
            float hp = Hold[(size_t)b * HID + j];
            Hnew[(size_t)b * HID + j] = (1.0f - z) * n + z * hp;
        }
    }
}

// ---------------------------------------------------------------------------
// Head: y_t[b,d] = h2_new[b,:] . W_fc[d,:] + b_fc[d], written straight into
// d_out at [b, t, d].  Tile: 32b x 64d per block, 256 threads, 2b x 4d each.
__global__ void __launch_bounds__(256)
head_kernel(int cur, const float* __restrict__ Wfc,
            const float* __restrict__ bfc, float* __restrict__ out, int t) {
    const float* H2 = g_h2[cur ^ 1];

    const int tx = threadIdx.x;
    const int dl = (tx & 15) * 4;   // 0..60
    const int bl = (tx >> 4) * 2;   // 0..30
    const int b0 = blockIdx.x * 32;

    __shared__ float sH[32][17];
    __shared__ float sW[64][17];

    float acc[2][4] = {};
    for (int k0 = 0; k0 < HID; k0 += 16) {
        for (int idx = tx; idx < 32 * 16; idx += 256) {
            int b = idx >> 4, k = idx & 15;
            sH[b][k] = H2[(size_t)(b0 + b) * HID + k0 + k];
        }
        for (int idx = tx; idx < 64 * 16; idx += 256) {
            int d = idx >> 4, k = idx & 15;
            sW[d][k] = Wfc[(size_t)d * HID + k0 + k];
        }
        __syncthreads();
        #pragma unroll
        for (int kk = 0; kk < 16; kk++) {
            float hv[2], wv[4];
            hv[0] = sH[bl][kk];
            hv[1] = sH[bl + 1][kk];
            #pragma unroll
            for (int c = 0; c < 4; c++) wv[c] = sW[dl + c][kk];
            #pragma unroll
            for (int i = 0; i < 2; i++)
                #pragma unroll
                for (int c = 0; c < 4; c++) acc[i][c] += hv[i] * wv[c];
        }
        __syncthreads();
    }
    #pragma unroll
    for (int i = 0; i < 2; i++) {
        int b = b0 + bl + i;
        #pragma unroll
        for (int c = 0; c < 4; c++) {
            int d = dl + c;
            out[((size_t)b * TSEQ + t) * DIN + d] = acc[i][c] + bfc[d];
        }
    }
}

// ---------------------------------------------------------------------------
extern "C" void kernel_launch(void* const* d_in, const int* in_sizes, int n_in,
                              void* d_out, int out_size) {
    (void)in_sizes; (void)n_in; (void)out_size;
    const float* x     = (const float*)d_in[0];
    const float* h1    = (const float*)d_in[1];
    const float* h2    = (const float*)d_in[2];
    const float* W_ih1 = (const float*)d_in[3];
    const float* W_hh1 = (const float*)d_in[4];
    const float* b_ih1 = (const float*)d_in[5];
    const float* b_hh1 = (const float*)d_in[6];
    const float* W_ih2 = (const float*)d_in[7];
    const float* W_hh2 = (const float*)d_in[8];
    const float* b_ih2 = (const float*)d_in[9];
    const float* b_hh2 = (const float*)d_in[10];
    const float* W_fc  = (const float*)d_in[11];
    const float* b_fc  = (const float*)d_in[12];
    float* out = (float*)d_out;

    init_states<<<512, 256>>>(h1, h2);

    dim3 lgrid(BATCH / 64, HID / 32);
    for (int t = 0; t < TSEQ; t++) {
        int cur = t & 1;
        // Layer 1: input x_t (batch row stride T*D)
        gru_layer<DIN><<<lgrid, 256>>>(x + (size_t)t * DIN, TSEQ * DIN, 0, cur,
                                       W_ih1, W_hh1, b_ih1, b_hh1);
        // Layer 2: input = new h1
        gru_layer<HID><<<lgrid, 256>>>(nullptr, HID, 1, cur,
                                       W_ih2, W_hh2, b_ih2, b_hh2);
        // Head: y_t from new h2
        head_kernel<<<BATCH / 32, 256>>>(cur, W_fc, b_fc, out, t);
    }
    // After t=255 (cur=1), final states live in slot 0.
    write_states<<<512, 256>>>(out + (size_t)BATCH * TSEQ * DIN);
}

// round 2
// speedup vs baseline: 7.4725x; 7.4725x over previous
#include <cuda_runtime.h>
#include <math.h>
#include <stdint.h>

#define B_    4096
#define T_    256
#define D_    64
#define H_    256
#define NBLK  128
#define MTILE 32
#define NTHR  256

// padded shared strides (floats); stride ≡ 8 (mod 32) => clean LDS.64 phases
#define S_H 264
#define S_X 72

// tf32-repacked weight blobs (+512 floats pad for prefetch overrun)
__device__ __align__(16) float g_bA1[8 * 4 * 12 * 128 + 512];   // W_ih1 (K=64)
__device__ __align__(16) float g_bH1[8 * 16 * 12 * 128 + 512];  // W_hh1 (K=256)
__device__ __align__(16) float g_bX2[8 * 16 * 12 * 128 + 512];  // W_ih2 (K=256)
__device__ __align__(16) float g_bH2[8 * 16 * 12 * 128 + 512];  // W_hh2 (K=256)
__device__ __align__(16) float g_bF [8 * 16 * 1 * 128 + 512];   // W_fc  (K=256)

__device__ __forceinline__ uint32_t f2tf(float f) {
    uint32_t u; asm("cvt.rna.tf32.f32 %0, %1;" : "=r"(u) : "f"(f)); return u;
}
__device__ __forceinline__ void mma8(float* d, const uint32_t* a, uint32_t b0, uint32_t b1) {
    asm volatile(
        "mma.sync.aligned.m16n8k8.row.col.f32.tf32.tf32.f32 "
        "{%0,%1,%2,%3}, {%4,%5,%6,%7}, {%8,%9}, {%0,%1,%2,%3};\n"
        : "+f"(d[0]), "+f"(d[1]), "+f"(d[2]), "+f"(d[3])
        : "r"(a[0]), "r"(a[1]), "r"(a[2]), "r"(a[3]), "r"(b0), "r"(b1));
}
__device__ __forceinline__ float fsig(float x) { return 1.0f / (1.0f + __expf(-x)); }
__device__ __forceinline__ int perm8(int k) { return 2 * (k & 3) + (k >> 2); }  // k in [0,8)

__device__ __forceinline__ float* blob_sel(int id) {
    switch (id) {
        case 0: return g_bA1;
        case 1: return g_bH1;
        case 2: return g_bX2;
        case 3: return g_bH2;
        default: return g_bF;
    }
}

// ---------------------------------------------------------------------------
// Repack W[3H x K] -> blob[w][c][t=(G*4+jt)][lane][4], tf32-rounded, so that a
// warp's B-fragments for one m16n8k8 pair are a single coalesced LDG.128.
__global__ void repack_layer(const float* __restrict__ W, int K, int id) {
    float* blob = blob_sel(id);
    int K16 = K >> 4;
    int total = 8 * K16 * 12 * 32;  // float4 units
    for (int o = blockIdx.x * blockDim.x + threadIdx.x; o < total;
         o += gridDim.x * blockDim.x) {
        int lane = o & 31, s = o >> 5;
        int t = s % 12, c = (s / 12) % K16, w = s / (12 * K16);
        int G = t >> 2, jt = t & 3, gg = lane >> 2, tg = lane & 3;
        int n = G * H_ + w * 32 + jt * 8 + gg;
        const float* src = W + (size_t)n * K + c * 16 + tg;
        float4 v;
        v.x = __uint_as_float(f2tf(src[0]));
        v.y = __uint_as_float(f2tf(src[4]));
        v.z = __uint_as_float(f2tf(src[8]));
        v.w = __uint_as_float(f2tf(src[12]));
        reinterpret_cast<float4*>(blob)[o] = v;
    }
}
// W_fc[64 x 256] -> blob[w][c][lane][4]   (warp w owns out-cols w*8..w*8+7)
__global__ void repack_head(const float* __restrict__ W) {
    float* blob = g_bF;
    int total = 8 * 16 * 32;
    for (int o = blockIdx.x * blockDim.x + threadIdx.x; o < total;
         o += gridDim.x * blockDim.x) {
        int lane = o & 31, s = o >> 5;
        int c = s % 16, w = s / 16;
        int gg = lane >> 2, tg = lane & 3;
        int n = w * 8 + gg;
        const float* src = W + (size_t)n * 256 + c * 16 + tg;
        float4 v;
        v.x = __uint_as_float(f2tf(src[0]));
        v.y = __uint_as_float(f2tf(src[4]));
        v.z = __uint_as_float(f2tf(src[8]));
        v.w = __uint_as_float(f2tf(src[12]));
        reinterpret_cast<float4*>(blob)[o] = v;
    }
}

// ---------------------------------------------------------------------------
// One GEMM phase: acc[32rows x (3 gates x 32cols-per-warp)] += A[32,K] * W^T
// B frags streamed from L2 via LDG.128 (depth-4 ring prefetch).
template <int NK16, int ASTR>
__device__ __forceinline__ void gemm3(const float* __restrict__ sA,
                                      const float* __restrict__ blobWL,
                                      int g, int tig,
                                      float (&aR)[4][2][4], float (&aZ)[4][2][4],
                                      float (&aN)[4][2][4]) {
    const float4* pf = reinterpret_cast<const float4*>(blobWL);
    float4 buf[4];
#pragma unroll
    for (int i = 0; i < 4; i++) buf[i] = pf[i * 32];
    pf += 4 * 32;
    const float* sab = sA + g * ASTR + 2 * tig;
#pragma unroll 2
    for (int c = 0; c < NK16; c++) {
        uint32_t af[2][2][4];
#pragma unroll
        for (int m = 0; m < 2; m++)
#pragma unroll
            for (int k8 = 0; k8 < 2; k8++) {
                const float* p = sab + m * 16 * ASTR + c * 16 + k8 * 8;
                float2 lo = *reinterpret_cast<const float2*>(p);
                float2 hi = *reinterpret_cast<const float2*>(p + 8 * ASTR);
                af[m][k8][0] = f2tf(lo.x); af[m][k8][1] = f2tf(hi.x);
                af[m][k8][2] = f2tf(lo.y); af[m][k8][3] = f2tf(hi.y);
            }
#pragma unroll
        for (int t = 0; t < 12; t++) {
            float4 wv = buf[t & 3];
            buf[t & 3] = *pf;  pf += 32;   // prefetch tile s+4
            uint32_t b0 = __float_as_uint(wv.x), b1 = __float_as_uint(wv.y);
            uint32_t b2 = __float_as_uint(wv.z), b3 = __float_as_uint(wv.w);
            float (*acc)[2][4] = (t < 4) ? aR : (t < 8) ? aZ : aN;
            int jt = t & 3;
            mma8(acc[jt][0], af[0][0], b0, b1);
            mma8(acc[jt][1], af[1][0], b0, b1);
            mma8(acc[jt][0], af[0][1], b2, b3);
            mma8(acc[jt][1], af[1][1], b2, b3);
        }
    }
}

// Head GEMM: 8 out-cols per warp, K=256
__device__ __forceinline__ void gemmH(const float* __restrict__ sA,
                                      const float* __restrict__ blobWL,
                                      int g, int tig, float (&acc)[2][4]) {
    const float4* pf = reinterpret_cast<const float4*>(blobWL);
    float4 buf[4];
#pragma unroll
    for (int i = 0; i < 4; i++) buf[i] = pf[i * 32];
    pf += 4 * 32;
    const float* sab = sA + g * S_H + 2 * tig;
#pragma unroll 4
    for (int c = 0; c < 16; c++) {
        uint32_t af[2][2][4];
#pragma unroll
        for (int m = 0; m < 2; m++)
#pragma unroll
            for (int k8 = 0; k8 < 2; k8++) {
                const float* p = sab + m * 16 * S_H + c * 16 + k8 * 8;
                float2 lo = *reinterpret_cast<const float2*>(p);
                float2 hi = *reinterpret_cast<const float2*>(p + 8 * S_H);
                af[m][k8][0] = f2tf(lo.x); af[m][k8][1] = f2tf(hi.x);
                af[m][k8][2] = f2tf(lo.y); af[m][k8][3] = f2tf(hi.y);
            }
        float4 wv = buf[c & 3];
        buf[c & 3] = *pf;  pf += 32;
        uint32_t b0 = __float_as_uint(wv.x), b1 = __float_as_uint(wv.y);
        uint32_t b2 = __float_as_uint(wv.z), b3 = __float_as_uint(wv.w);
        mma8(acc[0], af[0][0], b0, b1);
        mma8(acc[1], af[1][0], b0, b1);
        mma8(acc[0], af[0][1], b2, b3);
        mma8(acc[1], af[1][1], b2, b3);
    }
}

__device__ __forceinline__ void zero3(float (&aR)[4][2][4], float (&aZ)[4][2][4],
                                      float (&aN)[4][2][4]) {
#pragma unroll
    for (int jt = 0; jt < 4; jt++)
#pragma unroll
        for (int m = 0; m < 2; m++)
#pragma unroll
            for (int q = 0; q < 4; q++) {
                aR[jt][m][q] = 0.f; aZ[jt][m][q] = 0.f; aN[jt][m][q] = 0.f;
            }
}

// stash i_n accumulators into h-next buffer (same cells the epilogue writes)
__device__ __forceinline__ void stash(float (&aN)[4][2][4], float* hn,
                                      int w, int g, int tig) {
    int pc0 = perm8(2 * tig), pc1 = perm8(2 * tig + 1);
#pragma unroll
    for (int jt = 0; jt < 4; jt++) {
        int cb = w * 32 + jt * 8;
#pragma unroll
        for (int m = 0; m < 2; m++) {
            int r0 = g + m * 16, r1 = g + 8 + m * 16;
            hn[r0 * S_H + cb + pc0] = aN[jt][m][0];
            hn[r0 * S_H + cb + pc1] = aN[jt][m][1];
            hn[r1 * S_H + cb + pc0] = aN[jt][m][2];
            hn[r1 * S_H + cb + pc1] = aN[jt][m][3];
            aN[jt][m][0] = 0.f; aN[jt][m][1] = 0.f;
            aN[jt][m][2] = 0.f; aN[jt][m][3] = 0.f;
        }
    }
}

// GRU gate math + in-place h update (hn currently holds stashed i_n)
__device__ __forceinline__ void epilogue(float (&aR)[4][2][4], float (&aZ)[4][2][4],
                                         float (&aN)[4][2][4],
                                         const float* __restrict__ hc, float* hn,
                                         const float* __restrict__ sB,
                                         int w, int g, int tig) {
    int pc0 = perm8(2 * tig), pc1 = perm8(2 * tig + 1);
#pragma unroll
    for (int jt = 0; jt < 4; jt++) {
        int j0 = w * 32 + jt * 8 + 2 * tig;
        float br0 = sB[j0],          br1 = sB[j0 + 1];
        float bz0 = sB[H_ + j0],     bz1 = sB[H_ + j0 + 1];
        float bi0 = sB[2 * H_ + j0], bi1 = sB[2 * H_ + j0 + 1];
        float bh0 = sB[3 * H_ + j0], bh1 = sB[3 * H_ + j0 + 1];
        int cb = w * 32 + jt * 8;
#pragma unroll
        for (int m = 0; m < 2; m++)
#pragma unroll
            for (int hq = 0; hq < 2; hq++) {
                int row = g + hq * 8 + m * 16;
                int q0 = hq * 2, q1 = hq * 2 + 1;
                int i0 = row * S_H + cb + pc0, i1 = row * S_H + cb + pc1;
                float r0 = fsig(aR[jt][m][q0] + br0);
                float r1 = fsig(aR[jt][m][q1] + br1);
                float z0 = fsig(aZ[jt][m][q0] + bz0);
                float z1 = fsig(aZ[jt][m][q1] + bz1);
                float n0 = tanhf(hn[i0] + bi0 + r0 * (aN[jt][m][q0] + bh0));
                float n1 = tanhf(hn[i1] + bi1 + r1 * (aN[jt][m][q1] + bh1));
                hn[i0] = (1.f - z0) * n0 + z0 * hc[i0];
                hn[i1] = (1.f - z1) * n1 + z1 * hc[i1];
            }
    }
}

// ---------------------------------------------------------------------------
extern __shared__ float smem[];

__global__ void __launch_bounds__(NTHR, 1)
gru_main(const float* __restrict__ x, const float* __restrict__ h1g,
         const float* __restrict__ h2g,
         const float* __restrict__ bih1, const float* __restrict__ bhh1,
         const float* __restrict__ bih2, const float* __restrict__ bhh2,
         const float* __restrict__ bfc, float* __restrict__ out) {
    float* sh1 = smem;                      // 2 * 32 * S_H
    float* sh2 = sh1 + 2 * MTILE * S_H;     // 2 * 32 * S_H
    float* sx  = sh2 + 2 * MTILE * S_H;     // 32 * S_X
    float* sB1 = sx + MTILE * S_X;          // 4 * 256
    float* sB2 = sB1 + 4 * H_;              // 4 * 256
    float* sBf = sB2 + 4 * H_;              // 64

    const int tid = threadIdx.x;
    const int w = tid >> 5, lane = tid & 31, g = lane >> 2, tig = lane & 3;
    const int b0 = blockIdx.x * MTILE;

    // biases combined into shared
    sB1[tid]          = bih1[tid] + bhh1[tid];
    sB1[H_ + tid]     = bih1[H_ + tid] + bhh1[H_ + tid];
    sB1[2 * H_ + tid] = bih1[2 * H_ + tid];
    sB1[3 * H_ + tid] = bhh1[2 * H_ + tid];
    sB2[tid]          = bih2[tid] + bhh2[tid];
    sB2[H_ + tid]     = bih2[H_ + tid] + bhh2[H_ + tid];
    sB2[2 * H_ + tid] = bih2[2 * H_ + tid];
    sB2[3 * H_ + tid] = bhh2[2 * H_ + tid];
    if (tid < D_) sBf[tid] = bfc[tid];

    // init h (buffer 0), k-permuted
    {
        int pc = (tid & ~7) | perm8(tid & 7);
        for (int i = 0; i < MTILE; i++) {
            sh1[i * S_H + pc] = h1g[(size_t)(b0 + i) * H_ + tid];
            sh2[i * S_H + pc] = h2g[(size_t)(b0 + i) * H_ + tid];
        }
    }

    // per-warp blob bases (lane folded in)
    const float* bA1 = g_bA1 + (size_t)w * 4 * 12 * 128 + lane * 4;
    const float* bH1 = g_bH1 + (size_t)w * 16 * 12 * 128 + lane * 4;
    const float* bX2 = g_bX2 + (size_t)w * 16 * 12 * 128 + lane * 4;
    const float* bH2 = g_bH2 + (size_t)w * 16 * 12 * 128 + lane * 4;
    const float* bF  = g_bF  + (size_t)w * 16 * 128 + lane * 4;

    float aR[4][2][4], aZ[4][2][4], aN[4][2][4];

    for (int t = 0; t < T_; t++) {
        const int cur = t & 1;
        float* h1c = sh1 + cur * MTILE * S_H;
        float* h1n = sh1 + (cur ^ 1) * MTILE * S_H;
        float* h2c = sh2 + cur * MTILE * S_H;
        float* h2n = sh2 + (cur ^ 1) * MTILE * S_H;

        // stage x_t (k-permuted)
        {
            int r = tid >> 3, c8 = (tid & 7) * 8;
            const float* xp = x + ((size_t)(b0 + r) * T_ + t) * D_ + c8;
            float4 v0 = *reinterpret_cast<const float4*>(xp);
            float4 v1 = *reinterpret_cast<const float4*>(xp + 4);
            float* dst = sx + r * S_X + c8;
            dst[0] = v0.x; dst[2] = v0.y; dst[4] = v0.z; dst[6] = v0.w;
            dst[1] = v1.x; dst[3] = v1.y; dst[5] = v1.z; dst[7] = v1.w;
        }
        __syncthreads();

        // ---- Layer 1 ----
        zero3(aR, aZ, aN);
        gemm3<4, S_X>(sx, bA1, g, tig, aR, aZ, aN);     // x-part (i_n in aN)
        stash(aN, h1n, w, g, tig);                      // park i_n, reuse aN
        gemm3<16, S_H>(h1c, bH1, g, tig, aR, aZ, aN);   // h-part (h_n in aN)
        epilogue(aR, aZ, aN, h1c, h1n, sB1, w, g, tig);
        __syncthreads();

        // ---- Layer 2 (input = new h1) ----
        zero3(aR, aZ, aN);
        gemm3<16, S_H>(h1n, bX2, g, tig, aR, aZ, aN);
        stash(aN, h2n, w, g, tig);
        gemm3<16, S_H>(h2c, bH2, g, tig, aR, aZ, aN);
        epilogue(aR, aZ, aN, h2c, h2n, sB2, w, g, tig);
        __syncthreads();

        // ---- Head: y_t = h2_new @ W_fc^T + b_fc ----
        {
            float aF[2][4];
#pragma unroll
            for (int m = 0; m < 2; m++)
#pragma unroll
                for (int q = 0; q < 4; q++) aF[m][q] = 0.f;
            gemmH(h2n, bF, g, tig, aF);
            int d0 = w * 8 + 2 * tig;
            float bs0 = sBf[d0], bs1 = sBf[d0 + 1];
#pragma unroll
            for (int m = 0; m < 2; m++) {
                int r0 = g + m * 16, r1 = g + 8 + m * 16;
                float2 v;
                v.x = aF[m][0] + bs0; v.y = aF[m][1] + bs1;
                *reinterpret_cast<float2*>(
                    out + ((size_t)(b0 + r0) * T_ + t) * D_ + d0) = v;
                v.x = aF[m][2] + bs0; v.y = aF[m][3] + bs1;
                *reinterpret_cast<float2*>(
                    out + ((size_t)(b0 + r1) * T_ + t) * D_ + d0) = v;
            }
        }
        // next iteration's sync-after-sx covers remaining hazards
    }
    __syncthreads();

    // final states (t=255 wrote buffer 0), un-permute
    {
        int pc = (tid & ~7) | perm8(tid & 7);
        size_t base = (size_t)B_ * T_ * D_;
        for (int i = 0; i < MTILE; i++) {
            out[base + (size_t)(b0 + i) * H_ + tid] = sh1[i * S_H + pc];
            out[base + (size_t)B_ * H_ + (size_t)(b0 + i) * H_ + tid] =
                sh2[i * S_H + pc];
        }
    }
}

// ---------------------------------------------------------------------------
extern "C" void kernel_launch(void* const* d_in, const int* in_sizes, int n_in,
                              void* d_out, int out_size) {
    (void)in_sizes; (void)n_in; (void)out_size;
    const float* x     = (const float*)d_in[0];
    const float* h1    = (const float*)d_in[1];
    const float* h2    = (const float*)d_in[2];
    const float* W_ih1 = (const float*)d_in[3];
    const float* W_hh1 = (const float*)d_in[4];
    const float* b_ih1 = (const float*)d_in[5];
    const float* b_hh1 = (const float*)d_in[6];
    const float* W_ih2 = (const float*)d_in[7];
    const float* W_hh2 = (const float*)d_in[8];
    const float* b_ih2 = (const float*)d_in[9];
    const float* b_hh2 = (const float*)d_in[10];
    const float* W_fc  = (const float*)d_in[11];
    const float* b_fc  = (const float*)d_in[12];
    float* out = (float*)d_out;

    repack_layer<<<48, 256>>>(W_ih1, 64, 0);
    repack_layer<<<192, 256>>>(W_hh1, 256, 1);
    repack_layer<<<192, 256>>>(W_ih2, 256, 2);
    repack_layer<<<192, 256>>>(W_hh2, 256, 3);
    repack_head<<<16, 256>>>(W_fc);

    const int smem_bytes =
        (2 * MTILE * S_H * 2 + MTILE * S_X + 4 * H_ * 2 + 64) * (int)sizeof(float);
    static int attr_set = 0;
    cudaFuncSetAttribute(gru_main, cudaFuncAttributeMaxDynamicSharedMemorySize,
                         smem_bytes);
    (void)attr_set;

    gru_main<<<NBLK, NTHR, smem_bytes>>>(x, h1, h2, b_ih1, b_hh1, b_ih2, b_hh2,
                                         b_fc, out);
}

// round 3
// speedup vs baseline: 12.4962x; 1.6723x over previous
#include <cuda_runtime.h>
#include <cuda_fp16.h>
#include <math.h>
#include <stdint.h>

#define B_    4096
#define T_    256
#define D_    64
#define H_    256
#define NBLK  128
#define MTILE 32
#define NTHR  256

// padded shared strides (floats); stride ≡ 8 (mod 32) => conflict-free LDS.64
#define S_H 264
#define S_X 72

// fp16-repacked weight blobs, uint4 = 8 fp16 = one lane's B-frags for n8 x k32
// (+256 uint4 pad for prefetch ring overrun)
__device__ __align__(16) uint4 g_bA1[8 * 2 * 12 * 32 + 256];  // W_ih1 (K=64)
__device__ __align__(16) uint4 g_bH1[8 * 8 * 12 * 32 + 256];  // W_hh1 (K=256)
__device__ __align__(16) uint4 g_bX2[8 * 8 * 12 * 32 + 256];  // W_ih2 (K=256)
__device__ __align__(16) uint4 g_bH2[8 * 8 * 12 * 32 + 256];  // W_hh2 (K=256)
__device__ __align__(16) uint4 g_bF [8 * 8 * 1 * 32 + 256];   // W_fc  (K=256)

__device__ __forceinline__ uint32_t h2u(__half2 h) {
    return *reinterpret_cast<uint32_t*>(&h);
}
__device__ __forceinline__ uint32_t pkh(float a, float b) {
    return h2u(__floats2half2_rn(a, b));
}
// fp16 MMA, fp32 accumulate: D(16x8) += A(16x16) * B(16x8)
__device__ __forceinline__ void mma16(float* d, const uint32_t* a,
                                      uint32_t b0, uint32_t b1) {
    asm volatile(
        "mma.sync.aligned.m16n8k16.row.col.f32.f16.f16.f32 "
        "{%0,%1,%2,%3}, {%4,%5,%6,%7}, {%8,%9}, {%0,%1,%2,%3};\n"
        : "+f"(d[0]), "+f"(d[1]), "+f"(d[2]), "+f"(d[3])
        : "r"(a[0]), "r"(a[1]), "r"(a[2]), "r"(a[3]), "r"(b0), "r"(b1));
}
__device__ __forceinline__ float fsig(float x) { return 1.0f / (1.0f + __expf(-x)); }

__device__ __forceinline__ uint4* blob_sel(int id) {
    switch (id) {
        case 0: return g_bA1;
        case 1: return g_bH1;
        case 2: return g_bX2;
        case 3: return g_bH2;
        default: return g_bF;
    }
}

// ---------------------------------------------------------------------------
// Repack W[3H x K] -> fp16 blob[w][c2][t][lane] so a warp's B-frags for one
// (n8 x k32) tile are one coalesced LDG.128.
// lane(g=lane>>2,tig=lane&3): .x={W[n][k+2tig],W[n][k+2tig+1]} .y=+8 .z=+16 .w=+24
__global__ void repack_layer(const float* __restrict__ W, int K, int id) {
    uint4* blob = blob_sel(id);
    int K32 = K >> 5;
    int total = 8 * K32 * 12 * 32;
    for (int o = blockIdx.x * blockDim.x + threadIdx.x; o < total;
         o += gridDim.x * blockDim.x) {
        int lane = o & 31, s = o >> 5;
        int t = s % 12, c2 = (s / 12) % K32, w = s / (12 * K32);
        int G = t >> 2, jt = t & 3, g = lane >> 2, tig = lane & 3;
        int n = G * H_ + w * 32 + jt * 8 + g;
        const float* src = W + (size_t)n * K + c2 * 32 + 2 * tig;
        uint4 v;
        v.x = pkh(src[0],  src[1]);
        v.y = pkh(src[8],  src[9]);
        v.z = pkh(src[16], src[17]);
        v.w = pkh(src[24], src[25]);
        blob[o] = v;
    }
}
// W_fc[64 x 256] -> blob[w][c2][lane] (warp w owns out-cols w*8..w*8+7)
__global__ void repack_head(const float* __restrict__ W) {
    uint4* blob = g_bF;
    int total = 8 * 8 * 32;
    for (int o = blockIdx.x * blockDim.x + threadIdx.x; o < total;
         o += gridDim.x * blockDim.x) {
        int lane = o & 31, s = o >> 5;
        int c2 = s & 7, w = s >> 3;
        int g = lane >> 2, tig = lane & 3;
        int n = w * 8 + g;
        const float* src = W + (size_t)n * 256 + c2 * 32 + 2 * tig;
        uint4 v;
        v.x = pkh(src[0],  src[1]);
        v.y = pkh(src[8],  src[9]);
        v.z = pkh(src[16], src[17]);
        v.w = pkh(src[24], src[25]);
        blob[o] = v;
    }
}

// ---------------------------------------------------------------------------
// One gate-GEMM phase: acc[32 rows x (3 gates x 32 cols/warp)] += A[32,K] * W^T
// B-frags streamed from L2 via LDG.128 depth-4 ring; A from smem (fp32->fp16).
template <int NK32, int ASTR>
__device__ __forceinline__ void gemm3(const float* __restrict__ sA,
                                      const uint4* __restrict__ blobWL,
                                      int g, int tig,
                                      float (&aR)[4][2][4], float (&aZ)[4][2][4],
                                      float (&aN)[4][2][4]) {
    const uint4* pf = blobWL;
    uint4 buf[4];
#pragma unroll
    for (int i = 0; i < 4; i++) buf[i] = pf[i * 32];
    pf += 4 * 32;
    const float* sab = sA + g * ASTR + 2 * tig;
#pragma unroll 2
    for (int c2 = 0; c2 < NK32; c2++) {
        uint32_t af[2][2][4];
#pragma unroll
        for (int m = 0; m < 2; m++)
#pragma unroll
            for (int ch = 0; ch < 2; ch++) {
                const float* p = sab + m * 16 * ASTR + c2 * 32 + ch * 16;
                float2 v0 = *reinterpret_cast<const float2*>(p);
                float2 v1 = *reinterpret_cast<const float2*>(p + 8 * ASTR);
                float2 v2 = *reinterpret_cast<const float2*>(p + 8);
                float2 v3 = *reinterpret_cast<const float2*>(p + 8 * ASTR + 8);
                af[m][ch][0] = pkh(v0.x, v0.y);
                af[m][ch][1] = pkh(v1.x, v1.y);
                af[m][ch][2] = pkh(v2.x, v2.y);
                af[m][ch][3] = pkh(v3.x, v3.y);
            }
#pragma unroll
        for (int t = 0; t < 12; t++) {
            uint4 wv = buf[t & 3];
            buf[t & 3] = *pf;  pf += 32;   // prefetch tile t+4
            float (*acc)[2][4] = (t < 4) ? aR : (t < 8) ? aZ : aN;
            int jt = t & 3;
            mma16(acc[jt][0], af[0][0], wv.x, wv.y);
            mma16(acc[jt][1], af[1][0], wv.x, wv.y);
            mma16(acc[jt][0], af[0][1], wv.z, wv.w);
            mma16(acc[jt][1], af[1][1], wv.z, wv.w);
        }
    }
}

// Head GEMM: 8 out-cols per warp, K=256
__device__ __forceinline__ void gemmH(const float* __restrict__ sA,
                                      const uint4* __restrict__ blobWL,
                                      int g, int tig, float (&acc)[2][4]) {
    const uint4* pf = blobWL;
    uint4 buf[4];
#pragma unroll
    for (int i = 0; i < 4; i++) buf[i] = pf[i * 32];
    pf += 4 * 32;
    const float* sab = sA + g * S_H + 2 * tig;
#pragma unroll 2
    for (int c2 = 0; c2 < 8; c2++) {
        uint32_t af[2][2][4];
#pragma unroll
        for (int m = 0; m < 2; m++)
#pragma unroll
            for (int ch = 0; ch < 2; ch++) {
                const float* p = sab + m * 16 * S_H + c2 * 32 + ch * 16;
                float2 v0 = *reinterpret_cast<const float2*>(p);
                float2 v1 = *reinterpret_cast<const float2*>(p + 8 * S_H);
                float2 v2 = *reinterpret_cast<const float2*>(p + 8);
                float2 v3 = *reinterpret_cast<const float2*>(p + 8 * S_H + 8);
                af[m][ch][0] = pkh(v0.x, v0.y);
                af[m][ch][1] = pkh(v1.x, v1.y);
                af[m][ch][2] = pkh(v2.x, v2.y);
                af[m][ch][3] = pkh(v3.x, v3.y);
            }
        uint4 wv = buf[c2 & 3];
        buf[c2 & 3] = *pf;  pf += 32;
        mma16(acc[0], af[0][0], wv.x, wv.y);
        mma16(acc[1], af[1][0], wv.x, wv.y);
        mma16(acc[0], af[0][1], wv.z, wv.w);
        mma16(acc[1], af[1][1], wv.z, wv.w);
    }
}

__device__ __forceinline__ void zero3(float (&aR)[4][2][4], float (&aZ)[4][2][4],
                                      float (&aN)[4][2][4]) {
#pragma unroll
    for (int jt = 0; jt < 4; jt++)
#pragma unroll
        for (int m = 0; m < 2; m++)
#pragma unroll
            for (int q = 0; q < 4; q++) {
                aR[jt][m][q] = 0.f; aZ[jt][m][q] = 0.f; aN[jt][m][q] = 0.f;
            }
}

// stash i_n accumulators into h-next buffer (same cells epilogue later writes)
__device__ __forceinline__ void stash(float (&aN)[4][2][4], float* hn,
                                      int w, int g, int tig) {
#pragma unroll
    for (int jt = 0; jt < 4; jt++) {
        int cb = w * 32 + jt * 8 + 2 * tig;
#pragma unroll
        for (int m = 0; m < 2; m++) {
            int r0 = g + m * 16, r1 = g + 8 + m * 16;
            hn[r0 * S_H + cb]     = aN[jt][m][0];
            hn[r0 * S_H + cb + 1] = aN[jt][m][1];
            hn[r1 * S_H + cb]     = aN[jt][m][2];
            hn[r1 * S_H + cb + 1] = aN[jt][m][3];
            aN[jt][m][0] = 0.f; aN[jt][m][1] = 0.f;
            aN[jt][m][2] = 0.f; aN[jt][m][3] = 0.f;
        }
    }
}

// GRU gate math + h update (hn currently holds stashed i_n in our cells)
__device__ __forceinline__ void epilogue(float (&aR)[4][2][4], float (&aZ)[4][2][4],
                                         float (&aN)[4][2][4],
                                         const float* __restrict__ hc, float* hn,
                                         const float* __restrict__ sB,
                                         int w, int g, int tig) {
#pragma unroll
    for (int jt = 0; jt < 4; jt++) {
        int j0 = w * 32 + jt * 8 + 2 * tig;
        float br0 = sB[j0],          br1 = sB[j0 + 1];
        float bz0 = sB[H_ + j0],     bz1 = sB[H_ + j0 + 1];
        float bi0 = sB[2 * H_ + j0], bi1 = sB[2 * H_ + j0 + 1];
        float bh0 = sB[3 * H_ + j0], bh1 = sB[3 * H_ + j0 + 1];
#pragma unroll
        for (int m = 0; m < 2; m++)
#pragma unroll
            for (int hq = 0; hq < 2; hq++) {
                int row = g + hq * 8 + m * 16;
                int q0 = hq * 2, q1 = hq * 2 + 1;
                int i0 = row * S_H + j0, i1 = i0 + 1;
                float r0 = fsig(aR[jt][m][q0] + br0);
                float r1 = fsig(aR[jt][m][q1] + br1);
                float z0 = fsig(aZ[jt][m][q0] + bz0);
                float z1 = fsig(aZ[jt][m][q1] + bz1);
                float n0 = tanhf(hn[i0] + bi0 + r0 * (aN[jt][m][q0] + bh0));
                float n1 = tanhf(hn[i1] + bi1 + r1 * (aN[jt][m][q1] + bh1));
                hn[i0] = (1.f - z0) * n0 + z0 * hc[i0];
                hn[i1] = (1.f - z1) * n1 + z1 * hc[i1];
            }
    }
}

// ---------------------------------------------------------------------------
extern __shared__ float smem[];

__global__ void __launch_bounds__(NTHR, 1)
gru_main(const float* __restrict__ x, const float* __restrict__ h1g,
         const float* __restrict__ h2g,
         const float* __restrict__ bih1, const float* __restrict__ bhh1,
         const float* __restrict__ bih2, const float* __restrict__ bhh2,
         const float* __restrict__ bfc, float* __restrict__ out) {
    float* sh1 = smem;                      // 2 * 32 * S_H
    float* sh2 = sh1 + 2 * MTILE * S_H;     // 2 * 32 * S_H
    float* sx  = sh2 + 2 * MTILE * S_H;     // 32 * S_X
    float* sB1 = sx + MTILE * S_X;          // 4 * 256
    float* sB2 = sB1 + 4 * H_;              // 4 * 256
    float* sBf = sB2 + 4 * H_;              // 64

    const int tid = threadIdx.x;
    const int w = tid >> 5, lane = tid & 31, g = lane >> 2, tig = lane & 3;
    const int b0 = blockIdx.x * MTILE;

    // combined biases into shared
    sB1[tid]          = bih1[tid] + bhh1[tid];
    sB1[H_ + tid]     = bih1[H_ + tid] + bhh1[H_ + tid];
    sB1[2 * H_ + tid] = bih1[2 * H_ + tid];
    sB1[3 * H_ + tid] = bhh1[2 * H_ + tid];
    sB2[tid]          = bih2[tid] + bhh2[tid];
    sB2[H_ + tid]     = bih2[H_ + tid] + bhh2[H_ + tid];
    sB2[2 * H_ + tid] = bih2[2 * H_ + tid];
    sB2[3 * H_ + tid] = bhh2[2 * H_ + tid];
    if (tid < D_) sBf[tid] = bfc[tid];

    // init h (buffer 0)
    for (int i = 0; i < MTILE; i++) {
        sh1[i * S_H + tid] = h1g[(size_t)(b0 + i) * H_ + tid];
        sh2[i * S_H + tid] = h2g[(size_t)(b0 + i) * H_ + tid];
    }

    // per-warp blob bases (lane folded in)
    const uint4* bA1 = g_bA1 + (size_t)w * 2 * 12 * 32 + lane;
    const uint4* bH1 = g_bH1 + (size_t)w * 8 * 12 * 32 + lane;
    const uint4* bX2 = g_bX2 + (size_t)w * 8 * 12 * 32 + lane;
    const uint4* bH2 = g_bH2 + (size_t)w * 8 * 12 * 32 + lane;
    const uint4* bF  = g_bF  + (size_t)w * 8 * 32 + lane;

    float aR[4][2][4], aZ[4][2][4], aN[4][2][4];

    for (int t = 0; t < T_; t++) {
        const int cur = t & 1;
        float* h1c = sh1 + cur * MTILE * S_H;
        float* h1n = sh1 + (cur ^ 1) * MTILE * S_H;
        float* h2c = sh2 + cur * MTILE * S_H;
        float* h2n = sh2 + (cur ^ 1) * MTILE * S_H;

        // stage x_t
        {
            int r = tid >> 3, c8 = (tid & 7) * 8;
            const float* xp = x + ((size_t)(b0 + r) * T_ + t) * D_ + c8;
            float4 v0 = *reinterpret_cast<const float4*>(xp);
            float4 v1 = *reinterpret_cast<const float4*>(xp + 4);
            float* dst = sx + r * S_X + c8;
            *reinterpret_cast<float4*>(dst)     = v0;
            *reinterpret_cast<float4*>(dst + 4) = v1;
        }
        __syncthreads();

        // ---- Layer 1 ----
        zero3(aR, aZ, aN);
        gemm3<2, S_X>(sx, bA1, g, tig, aR, aZ, aN);     // x-part (i_n in aN)
        stash(aN, h1n, w, g, tig);                      // park i_n, reuse aN
        gemm3<8, S_H>(h1c, bH1, g, tig, aR, aZ, aN);    // h-part (h_n in aN)
        epilogue(aR, aZ, aN, h1c, h1n, sB1, w, g, tig);
        __syncthreads();

        // ---- Layer 2 (input = new h1) ----
        zero3(aR, aZ, aN);
        gemm3<8, S_H>(h1n, bX2, g, tig, aR, aZ, aN);
        stash(aN, h2n, w, g, tig);
        gemm3<8, S_H>(h2c, bH2, g, tig, aR, aZ, aN);
        epilogue(aR, aZ, aN, h2c, h2n, sB2, w, g, tig);
        __syncthreads();

        // ---- Head: y_t = h2_new @ W_fc^T + b_fc ----
        {
            float aF[2][4];
#pragma unroll
            for (int m = 0; m < 2; m++)
#pragma unroll
                for (int q = 0; q < 4; q++) aF[m][q] = 0.f;
            gemmH(h2n, bF, g, tig, aF);
            int d0 = w * 8 + 2 * tig;
            float bs0 = sBf[d0], bs1 = sBf[d0 + 1];
#pragma unroll
            for (int m = 0; m < 2; m++) {
                int r0 = g + m * 16, r1 = g + 8 + m * 16;
                float2 v;
                v.x = aF[m][0] + bs0; v.y = aF[m][1] + bs1;
                *reinterpret_cast<float2*>(
                    out + ((size_t)(b0 + r0) * T_ + t) * D_ + d0) = v;
                v.x = aF[m][2] + bs0; v.y = aF[m][3] + bs1;
                *reinterpret_cast<float2*>(
                    out + ((size_t)(b0 + r1) * T_ + t) * D_ + d0) = v;
            }
        }
        // next iteration's post-stage sync covers remaining hazards
    }
    __syncthreads();

    // final states (t=255 wrote buffer 0)
    {
        size_t base = (size_t)B_ * T_ * D_;
        for (int i = 0; i < MTILE; i++) {
            out[base + (size_t)(b0 + i) * H_ + tid] = sh1[i * S_H + tid];
            out[base + (size_t)B_ * H_ + (size_t)(b0 + i) * H_ + tid] =
                sh2[i * S_H + tid];
        }
    }
}

// ---------------------------------------------------------------------------
extern "C" void kernel_launch(void* const* d_in, const int* in_sizes, int n_in,
                              void* d_out, int out_size) {
    (void)in_sizes; (void)n_in; (void)out_size;
    const float* x     = (const float*)d_in[0];
    const float* h1    = (const float*)d_in[1];
    const float* h2    = (const float*)d_in[2];
    const float* W_ih1 = (const float*)d_in[3];
    const float* W_hh1 = (const float*)d_in[4];
    const float* b_ih1 = (const float*)d_in[5];
    const float* b_hh1 = (const float*)d_in[6];
    const float* W_ih2 = (const float*)d_in[7];
    const float* W_hh2 = (const float*)d_in[8];
    const float* b_ih2 = (const float*)d_in[9];
    const float* b_hh2 = (const float*)d_in[10];
    const float* W_fc  = (const float*)d_in[11];
    const float* b_fc  = (const float*)d_in[12];
    float* out = (float*)d_out;

    repack_layer<<<24, 256>>>(W_ih1, 64, 0);
    repack_layer<<<96, 256>>>(W_hh1, 256, 1);
    repack_layer<<<96, 256>>>(W_ih2, 256, 2);
    repack_layer<<<96, 256>>>(W_hh2, 256, 3);
    repack_head<<<8, 256>>>(W_fc);

    const int smem_bytes =
        (2 * MTILE * S_H * 2 + MTILE * S_X + 4 * H_ * 2 + 64) * (int)sizeof(float);
    cudaFuncSetAttribute(gru_main, cudaFuncAttributeMaxDynamicSharedMemorySize,
                         smem_bytes);

    gru_main<<<NBLK, NTHR, smem_bytes>>>(x, h1, h2, b_ih1, b_hh1, b_ih2, b_hh2,
                                         b_fc, out);
}

// round 4
// speedup vs baseline: 19.1540x; 1.5328x over previous
#include <cuda_runtime.h>
#include <cuda_fp16.h>
#include <math.h>
#include <stdint.h>

#define B_    4096
#define T_    256
#define D_    64
#define H_    256
#define NBLK  128
#define MTILE 32
#define NTHR  256

// padded shared strides (floats); stride ≡ 8 (mod 32) => conflict-free LDS.64
#define S_H 264
#define S_X 72

// Combined per-layer fp16 weight blobs. Layout:
//   blob[w][c2 0..NC-1][t 0..11][lane], uint4 = 8 fp16 = lane's B-frag (n8 x k32)
//   t = G*4 + jt : G=gate(r,z,n), jt = n8-tile within warp's 32 cols.
// L1: NC = 2 (Wih1, K=64) + 8 (Whh1) = 10.  L2: NC = 8 + 8 = 16.
// +512 uint4 pad for ring prefetch overrun.
__device__ __align__(16) uint4 g_bL1[8 * 10 * 12 * 32 + 512];
__device__ __align__(16) uint4 g_bL2[8 * 16 * 12 * 32 + 512];
__device__ __align__(16) uint4 g_bF [8 * 8 * 32 + 512];       // W_fc (K=256)

__device__ __forceinline__ uint32_t pkh(float a, float b) {
    __half2 h = __floats2half2_rn(a, b);
    return *reinterpret_cast<uint32_t*>(&h);
}
// fp16 MMA, fp32 accumulate: D(16x8) += A(16x16) * B(16x8)
__device__ __forceinline__ void mma16(float* d, const uint32_t* a,
                                      uint32_t b0, uint32_t b1) {
    asm volatile(
        "mma.sync.aligned.m16n8k16.row.col.f32.f16.f16.f32 "
        "{%0,%1,%2,%3}, {%4,%5,%6,%7}, {%8,%9}, {%0,%1,%2,%3};\n"
        : "+f"(d[0]), "+f"(d[1]), "+f"(d[2]), "+f"(d[3])
        : "r"(a[0]), "r"(a[1]), "r"(a[2]), "r"(a[3]), "r"(b0), "r"(b1));
}
__device__ __forceinline__ float ftanh(float x) {
    float y; asm("tanh.approx.f32 %0, %1;" : "=f"(y) : "f"(x)); return y;
}
__device__ __forceinline__ float fsig(float x) {
    return fmaf(0.5f, ftanh(0.5f * x), 0.5f);
}

// ---------------------------------------------------------------------------
// Repack combined layer blob: Wx[3H x Kx] then Wh[3H x 256].
__global__ void repack_comb(const float* __restrict__ Wx,
                            const float* __restrict__ Wh, int Kx, int id) {
    uint4* blob = (id == 0) ? g_bL1 : g_bL2;
    int CX = Kx >> 5;
    int NC = CX + 8;
    int total = 8 * NC * 12 * 32;
    for (int o = blockIdx.x * blockDim.x + threadIdx.x; o < total;
         o += gridDim.x * blockDim.x) {
        int lane = o & 31, s = o >> 5;
        int t = s % 12, c2 = (s / 12) % NC, w = s / (12 * NC);
        int G = t >> 2, jt = t & 3, g = lane >> 2, tig = lane & 3;
        int n = G * H_ + w * 32 + jt * 8 + g;
        const float* src = (c2 < CX)
            ? Wx + (size_t)n * Kx + c2 * 32 + 2 * tig
            : Wh + (size_t)n * 256 + (c2 - CX) * 32 + 2 * tig;
        uint4 v;
        v.x = pkh(src[0],  src[1]);
        v.y = pkh(src[8],  src[9]);
        v.z = pkh(src[16], src[17]);
        v.w = pkh(src[24], src[25]);
        blob[o] = v;
    }
}
// W_fc[64 x 256] -> blob[w][c2][lane] (warp w owns out-cols w*8..w*8+7)
__global__ void repack_head(const float* __restrict__ W) {
    uint4* blob = g_bF;
    int total = 8 * 8 * 32;
    for (int o = blockIdx.x * blockDim.x + threadIdx.x; o < total;
         o += gridDim.x * blockDim.x) {
        int lane = o & 31, s = o >> 5;
        int c2 = s & 7, w = s >> 3;
        int g = lane >> 2, tig = lane & 3;
        int n = w * 8 + g;
        const float* src = W + (size_t)n * 256 + c2 * 32 + 2 * tig;
        uint4 v;
        v.x = pkh(src[0],  src[1]);
        v.y = pkh(src[8],  src[9]);
        v.z = pkh(src[16], src[17]);
        v.w = pkh(src[24], src[25]);
        blob[o] = v;
    }
}

// ---------------------------------------------------------------------------
// One K-segment of a gate GEMM, ring depth 12 (statically indexed).
// sab = sA + g*ASTR + 2*tig precomputed by caller.
template <int NC2, int ASTR>
__device__ __forceinline__ void gemm_part(const float* __restrict__ sab,
                                          const uint4*& pf, uint4 (&buf)[12],
                                          float (&aR)[4][2][4],
                                          float (&aZ)[4][2][4],
                                          float (&aN)[4][2][4]) {
#pragma unroll 1
    for (int c2 = 0; c2 < NC2; c2++) {
        uint32_t af[2][2][4];
#pragma unroll
        for (int m = 0; m < 2; m++)
#pragma unroll
            for (int ch = 0; ch < 2; ch++) {
                const float* p = sab + m * 16 * ASTR + c2 * 32 + ch * 16;
                float2 v0 = *reinterpret_cast<const float2*>(p);
                float2 v1 = *reinterpret_cast<const float2*>(p + 8 * ASTR);
                float2 v2 = *reinterpret_cast<const float2*>(p + 8);
                float2 v3 = *reinterpret_cast<const float2*>(p + 8 * ASTR + 8);
                af[m][ch][0] = pkh(v0.x, v0.y);
                af[m][ch][1] = pkh(v1.x, v1.y);
                af[m][ch][2] = pkh(v2.x, v2.y);
                af[m][ch][3] = pkh(v3.x, v3.y);
            }
#pragma unroll
        for (int t = 0; t < 12; t++) {
            uint4 wv = buf[t];
            buf[t] = *pf;  pf += 32;       // prefetch distance = 12
            float (*acc)[2][4] = (t < 4) ? aR : (t < 8) ? aZ : aN;
            int jt = t & 3;
            mma16(acc[jt][0], af[0][0], wv.x, wv.y);
            mma16(acc[jt][1], af[1][0], wv.x, wv.y);
            mma16(acc[jt][0], af[0][1], wv.z, wv.w);
            mma16(acc[jt][1], af[1][1], wv.z, wv.w);
        }
    }
}

// Full layer GEMM: x-part (CX chunks, A=sA1) then h-part (8 chunks, A=sA2),
// one continuous weight stream with a single warm ring.
template <int CX, int ASTR1>
__device__ __forceinline__ void gemmL(const float* __restrict__ sA1,
                                      const float* __restrict__ sA2,
                                      const uint4* __restrict__ blobWL,
                                      int g, int tig,
                                      float (&aR)[4][2][4], float (&aZ)[4][2][4],
                                      float (&aNi)[4][2][4],
                                      float (&aNh)[4][2][4]) {
    const uint4* pf = blobWL;
    uint4 buf[12];
#pragma unroll
    for (int i = 0; i < 12; i++) buf[i] = pf[i * 32];
    pf += 12 * 32;
    const float* sab1 = sA1 + g * ASTR1 + 2 * tig;
    const float* sab2 = sA2 + g * S_H + 2 * tig;
    gemm_part<CX, ASTR1>(sab1, pf, buf, aR, aZ, aNi);
    gemm_part<8, S_H>(sab2, pf, buf, aR, aZ, aNh);
}

// Head GEMM: 8 out-cols per warp, K=256, ring depth 4 fully unrolled.
__device__ __forceinline__ void gemmH(const float* __restrict__ sA,
                                      const uint4* __restrict__ blobWL,
                                      int g, int tig, float (&acc)[2][4]) {
    const uint4* pf = blobWL;
    uint4 buf[4];
#pragma unroll
    for (int i = 0; i < 4; i++) buf[i] = pf[i * 32];
    pf += 4 * 32;
    const float* sab = sA + g * S_H + 2 * tig;
#pragma unroll
    for (int c2 = 0; c2 < 8; c2++) {
        uint32_t af[2][2][4];
#pragma unroll
        for (int m = 0; m < 2; m++)
#pragma unroll
            for (int ch = 0; ch < 2; ch++) {
                const float* p = sab + m * 16 * S_H + c2 * 32 + ch * 16;
                float2 v0 = *reinterpret_cast<const float2*>(p);
                float2 v1 = *reinterpret_cast<const float2*>(p + 8 * S_H);
                float2 v2 = *reinterpret_cast<const float2*>(p + 8);
                float2 v3 = *reinterpret_cast<const float2*>(p + 8 * S_H + 8);
                af[m][ch][0] = pkh(v0.x, v0.y);
                af[m][ch][1] = pkh(v1.x, v1.y);
                af[m][ch][2] = pkh(v2.x, v2.y);
                af[m][ch][3] = pkh(v3.x, v3.y);
            }
        uint4 wv = buf[c2 & 3];
        buf[c2 & 3] = *pf;  pf += 32;
        mma16(acc[0], af[0][0], wv.x, wv.y);
        mma16(acc[1], af[1][0], wv.x, wv.y);
        mma16(acc[0], af[0][1], wv.z, wv.w);
        mma16(acc[1], af[1][1], wv.z, wv.w);
    }
}

__device__ __forceinline__ void zero4(float (&aR)[4][2][4], float (&aZ)[4][2][4],
                                      float (&aNi)[4][2][4],
                                      float (&aNh)[4][2][4]) {
#pragma unroll
    for (int jt = 0; jt < 4; jt++)
#pragma unroll
        for (int m = 0; m < 2; m++)
#pragma unroll
            for (int q = 0; q < 4; q++) {
                aR[jt][m][q] = 0.f; aZ[jt][m][q] = 0.f;
                aNi[jt][m][q] = 0.f; aNh[jt][m][q] = 0.f;
            }
}

// GRU gate math + h update; all four pre-activation sets live in registers.
__device__ __forceinline__ void epilogue(float (&aR)[4][2][4], float (&aZ)[4][2][4],
                                         float (&aNi)[4][2][4],
                                         float (&aNh)[4][2][4],
                                         const float* __restrict__ hc, float* hn,
                                         const float* __restrict__ sB,
                                         int w, int g, int tig) {
#pragma unroll
    for (int jt = 0; jt < 4; jt++) {
        int j0 = w * 32 + jt * 8 + 2 * tig;
        float br0 = sB[j0],          br1 = sB[j0 + 1];
        float bz0 = sB[H_ + j0],     bz1 = sB[H_ + j0 + 1];
        float bi0 = sB[2 * H_ + j0], bi1 = sB[2 * H_ + j0 + 1];
        float bh0 = sB[3 * H_ + j0], bh1 = sB[3 * H_ + j0 + 1];
#pragma unroll
        for (int m = 0; m < 2; m++)
#pragma unroll
            for (int hq = 0; hq < 2; hq++) {
                int row = g + hq * 8 + m * 16;
                int q0 = hq * 2, q1 = hq * 2 + 1;
                int i0 = row * S_H + j0, i1 = i0 + 1;
                float r0 = fsig(aR[jt][m][q0] + br0);
                float r1 = fsig(aR[jt][m][q1] + br1);
                float z0 = fsig(aZ[jt][m][q0] + bz0);
                float z1 = fsig(aZ[jt][m][q1] + bz1);
                float n0 = ftanh(aNi[jt][m][q0] + bi0 + r0 * (aNh[jt][m][q0] + bh0));
                float n1 = ftanh(aNi[jt][m][q1] + bi1 + r1 * (aNh[jt][m][q1] + bh1));
                hn[i0] = (1.f - z0) * n0 + z0 * hc[i0];
                hn[i1] = (1.f - z1) * n1 + z1 * hc[i1];
            }
    }
}

// ---------------------------------------------------------------------------
extern __shared__ float smem[];

__global__ void __launch_bounds__(NTHR, 1)
gru_main(const float* __restrict__ x, const float* __restrict__ h1g,
         const float* __restrict__ h2g,
         const float* __restrict__ bih1, const float* __restrict__ bhh1,
         const float* __restrict__ bih2, const float* __restrict__ bhh2,
         const float* __restrict__ bfc, float* __restrict__ out) {
    float* sh1 = smem;                      // 2 * 32 * S_H
    float* sh2 = sh1 + 2 * MTILE * S_H;     // 2 * 32 * S_H
    float* sx  = sh2 + 2 * MTILE * S_H;     // 2 * 32 * S_X (double buffered)
    float* sB1 = sx + 2 * MTILE * S_X;      // 4 * 256
    float* sB2 = sB1 + 4 * H_;              // 4 * 256
    float* sBf = sB2 + 4 * H_;              // 64

    const int tid = threadIdx.x;
    const int w = tid >> 5, lane = tid & 31, g = lane >> 2, tig = lane & 3;
    const int b0 = blockIdx.x * MTILE;

    // combined biases into shared
    sB1[tid]          = bih1[tid] + bhh1[tid];
    sB1[H_ + tid]     = bih1[H_ + tid] + bhh1[H_ + tid];
    sB1[2 * H_ + tid] = bih1[2 * H_ + tid];
    sB1[3 * H_ + tid] = bhh1[2 * H_ + tid];
    sB2[tid]          = bih2[tid] + bhh2[tid];
    sB2[H_ + tid]     = bih2[H_ + tid] + bhh2[H_ + tid];
    sB2[2 * H_ + tid] = bih2[2 * H_ + tid];
    sB2[3 * H_ + tid] = bhh2[2 * H_ + tid];
    if (tid < D_) sBf[tid] = bfc[tid];

    // init h (buffer 0)
    for (int i = 0; i < MTILE; i++) {
        sh1[i * S_H + tid] = h1g[(size_t)(b0 + i) * H_ + tid];
        sh2[i * S_H + tid] = h2g[(size_t)(b0 + i) * H_ + tid];
    }

    // x staging coords for this thread
    const int xr = tid >> 3, xc = (tid & 7) * 8;
    const float* xbase = x + ((size_t)(b0 + xr) * T_) * D_ + xc;

    // stage x_0 into buffer 0
    {
        float4 v0 = *reinterpret_cast<const float4*>(xbase);
        float4 v1 = *reinterpret_cast<const float4*>(xbase + 4);
        float* dst = sx + xr * S_X + xc;
        *reinterpret_cast<float4*>(dst)     = v0;
        *reinterpret_cast<float4*>(dst + 4) = v1;
    }

    // per-warp blob bases (lane folded in)
    const uint4* bL1 = g_bL1 + (size_t)w * 10 * 12 * 32 + lane;
    const uint4* bL2 = g_bL2 + (size_t)w * 16 * 12 * 32 + lane;
    const uint4* bF  = g_bF  + (size_t)w * 8 * 32 + lane;

    float aR[4][2][4], aZ[4][2][4], aNi[4][2][4], aNh[4][2][4];

    for (int t = 0; t < T_; t++) {
        const int cur = t & 1;
        float* h1c = sh1 + cur * MTILE * S_H;
        float* h1n = sh1 + (cur ^ 1) * MTILE * S_H;
        float* h2c = sh2 + cur * MTILE * S_H;
        float* h2n = sh2 + (cur ^ 1) * MTILE * S_H;
        float* sxc = sx + cur * MTILE * S_X;
        float* sxn = sx + (cur ^ 1) * MTILE * S_X;

        __syncthreads();   // sx[cur] staged, previous-step h writes visible

        // issue x_{t+1} loads early (consumed at end of step)
        float4 vx0, vx1;
        if (t + 1 < T_) {
            const float* xp = xbase + (size_t)(t + 1) * D_;
            vx0 = *reinterpret_cast<const float4*>(xp);
            vx1 = *reinterpret_cast<const float4*>(xp + 4);
        }

        // ---- Layer 1 (single fused K=64+256 weight stream) ----
        zero4(aR, aZ, aNi, aNh);
        gemmL<2, S_X>(sxc, h1c, bL1, g, tig, aR, aZ, aNi, aNh);
        epilogue(aR, aZ, aNi, aNh, h1c, h1n, sB1, w, g, tig);
        __syncthreads();

        // ---- Layer 2 (input = new h1; fused K=256+256) ----
        zero4(aR, aZ, aNi, aNh);
        gemmL<8, S_H>(h1n, h2c, bL2, g, tig, aR, aZ, aNi, aNh);
        epilogue(aR, aZ, aNi, aNh, h2c, h2n, sB2, w, g, tig);
        __syncthreads();

        // ---- Head: y_t = h2_new @ W_fc^T + b_fc ----
        {
            float aF[2][4];
#pragma unroll
            for (int m = 0; m < 2; m++)
#pragma unroll
                for (int q = 0; q < 4; q++) aF[m][q] = 0.f;
            gemmH(h2n, bF, g, tig, aF);
            int d0 = w * 8 + 2 * tig;
            float bs0 = sBf[d0], bs1 = sBf[d0 + 1];
#pragma unroll
            for (int m = 0; m < 2; m++) {
                int r0 = g + m * 16, r1 = g + 8 + m * 16;
                float2 v;
                v.x = aF[m][0] + bs0; v.y = aF[m][1] + bs1;
                *reinterpret_cast<float2*>(
                    out + ((size_t)(b0 + r0) * T_ + t) * D_ + d0) = v;
                v.x = aF[m][2] + bs0; v.y = aF[m][3] + bs1;
                *reinterpret_cast<float2*>(
                    out + ((size_t)(b0 + r1) * T_ + t) * D_ + d0) = v;
            }
        }

        // park x_{t+1} into the other sx buffer
        if (t + 1 < T_) {
            float* dst = sxn + xr * S_X + xc;
            *reinterpret_cast<float4*>(dst)     = vx0;
            *reinterpret_cast<float4*>(dst + 4) = vx1;
        }
    }
    __syncthreads();

    // final states (t=255 wrote buffer 0)
    {
        size_t base = (size_t)B_ * T_ * D_;
        for (int i = 0; i < MTILE; i++) {
            out[base + (size_t)(b0 + i) * H_ + tid] = sh1[i * S_H + tid];
            out[base + (size_t)B_ * H_ + (size_t)(b0 + i) * H_ + tid] =
                sh2[i * S_H + tid];
        }
    }
}

// ---------------------------------------------------------------------------
extern "C" void kernel_launch(void* const* d_in, const int* in_sizes, int n_in,
                              void* d_out, int out_size) {
    (void)in_sizes; (void)n_in; (void)out_size;
    const float* x     = (const float*)d_in[0];
    const float* h1    = (const float*)d_in[1];
    const float* h2    = (const float*)d_in[2];
    const float* W_ih1 = (const float*)d_in[3];
    const float* W_hh1 = (const float*)d_in[4];
    const float* b_ih1 = (const float*)d_in[5];
    const float* b_hh1 = (const float*)d_in[6];
    const float* W_ih2 = (const float*)d_in[7];
    const float* W_hh2 = (const float*)d_in[8];
    const float* b_ih2 = (const float*)d_in[9];
    const float* b_hh2 = (const float*)d_in[10];
    const float* W_fc  = (const float*)d_in[11];
    const float* b_fc  = (const float*)d_in[12];
    float* out = (float*)d_out;

    repack_comb<<<120, 256>>>(W_ih1, W_hh1, 64, 0);
    repack_comb<<<192, 256>>>(W_ih2, W_hh2, 256, 1);
    repack_head<<<8, 256>>>(W_fc);

    const int smem_bytes =
        (2 * MTILE * S_H * 2 + 2 * MTILE * S_X + 4 * H_ * 2 + 64) *
        (int)sizeof(float);
    cudaFuncSetAttribute(gru_main, cudaFuncAttributeMaxDynamicSharedMemorySize,
                         smem_bytes);

    gru_main<<<NBLK, NTHR, smem_bytes>>>(x, h1, h2, b_ih1, b_hh1, b_ih2, b_hh2,
                                         b_fc, out);
}